// round 7
// baseline (speedup 1.0000x reference)
#include <cuda_runtime.h>
#include <cuda_bf16.h>
#include <math_constants.h>

// ---------------------------------------------------------------------------
// DGCNN forward, B=8 C=3 N=2048 k=20, emb dims 64/64/128/256/512.
// Full fp32 throughout (reference executes fp32 einsums). kNN distance
// evaluation order bit-matches the reference:
//   xx   : elementwise mul + plain adds (no FMA)
//   dot  : FMA chain over the 3-dim axis (GEMM-style)
//   dist : ((2*dot - xx_i) - xx_j) with explicit rn subs
// top_k ties -> lower index (jax.lax.top_k stable order).
// ---------------------------------------------------------------------------

#define BATCH 8
#define NPTS  2048
#define KNN   20
#define Q     (BATCH * NPTS)        // 16384 (b,n) pairs
#define P1    (Q * KNN)             // 327680 (b,n,k) columns

__device__ int    g_idx[P1];
__device__ float  g_y1[(size_t)64  * P1];
__device__ float  g_y2[(size_t)64  * P1];
__device__ float  g_y3[(size_t)128 * P1];
__device__ float  g_y4[(size_t)256 * P1];
__device__ float  g_xcat[(size_t)512 * Q];
__device__ float  g_y5[(size_t)512 * Q];
__device__ double g_sum[1024];
__device__ double g_sumsq[1024];
__device__ float  g_scale[1024];
__device__ float  g_shift[1024];

// ---------------------------------------------------------------------------
// kNN: one warp per query. Distances in smem, 20 iterative argmax passes
// (tie -> lower index, matching jax.lax.top_k).
// ---------------------------------------------------------------------------
__global__ void knn_kernel(const float* __restrict__ x, int* __restrict__ idx_out) {
    __shared__ float sd[4][NPTS];
    const int warp = threadIdx.x >> 5;
    const int lane = threadIdx.x & 31;
    const int query = blockIdx.x * 4 + warp;
    const int b = query >> 11;
    const int i = query & (NPTS - 1);
    const float* xb = x + (size_t)b * 3 * NPTS;

    const float xi0 = xb[i], xi1 = xb[NPTS + i], xi2 = xb[2 * NPTS + i];
    // xx_i: elementwise squares then plain adds (matches jnp.sum(x*x, axis=1))
    const float xxi = __fadd_rn(__fadd_rn(__fmul_rn(xi0, xi0), __fmul_rn(xi1, xi1)),
                                __fmul_rn(xi2, xi2));

    float* d = sd[warp];
    for (int j = lane; j < NPTS; j += 32) {
        float a0 = xb[j], a1 = xb[NPTS + j], a2 = xb[2 * NPTS + j];
        float xxj = __fadd_rn(__fadd_rn(__fmul_rn(a0, a0), __fmul_rn(a1, a1)),
                              __fmul_rn(a2, a2));
        // GEMM-style FMA chain over the contraction axis
        float dot = fmaf(xi2, a2, fmaf(xi1, a1, __fmul_rn(xi0, a0)));
        // dist = (-xx_i - (-2*dot)) - xx_j ; 2*dot scaling is exact
        d[j] = __fsub_rn(__fsub_rn(2.0f * dot, xxi), xxj);
    }
    __syncwarp();

    int* out = idx_out + query * KNN;
    for (int t = 0; t < KNN; t++) {
        float best = -CUDART_INF_F;
        int bi = NPTS;
        for (int j = lane; j < NPTS; j += 32) {
            float v = d[j];
            if (v > best) { best = v; bi = j; }      // ascending j keeps lower idx
        }
        #pragma unroll
        for (int off = 16; off; off >>= 1) {
            float ov = __shfl_xor_sync(0xffffffffu, best, off);
            int   oi = __shfl_xor_sync(0xffffffffu, bi, off);
            if (ov > best || (ov == best && oi < bi)) { best = ov; bi = oi; }
        }
        if (lane == 0) { out[t] = bi; d[bi] = -CUDART_INF_F; }
        __syncwarp();
    }
}

// ---------------------------------------------------------------------------
// Layer 1: gather edge feature (Cin=6) + 64x6 matvec per column, raw y out.
// ---------------------------------------------------------------------------
__global__ void layer1_kernel(const float* __restrict__ x, const int* __restrict__ idx,
                              const float* __restrict__ w1, float* __restrict__ y1) {
    __shared__ float ws[64 * 6];
    const int tid = threadIdx.x;
    for (int t = tid; t < 64 * 6; t += 256) ws[t] = w1[t];
    __syncthreads();

    const int p = blockIdx.x * 256 + tid;
    const int q = p / KNN;
    const int b = q >> 11;
    const int n = q & (NPTS - 1);
    const int j = idx[p];
    const float* xb = x + (size_t)b * 3 * NPTS;

    const float xi0 = xb[n], xi1 = xb[NPTS + n], xi2 = xb[2 * NPTS + n];
    const float f0 = xb[j] - xi0;
    const float f1 = xb[NPTS + j] - xi1;
    const float f2 = xb[2 * NPTS + j] - xi2;
    const float f3 = xi0, f4 = xi1, f5 = xi2;

    #pragma unroll 8
    for (int o = 0; o < 64; o++) {
        const float* w = ws + o * 6;
        float acc = fmaf(w[5], f5, fmaf(w[4], f4, fmaf(w[3], f3,
                    fmaf(w[2], f2, fmaf(w[1], f1, w[0] * f0)))));
        y1[(size_t)o * P1 + p] = acc;
    }
}

// ---------------------------------------------------------------------------
// Generic SGEMM: Y[O,P] = W[O,Cin] * act(X[Cin,P]); act = relu(x*scale+shift)
// when scale != nullptr (BN of previous layer folded on load).
// Tiles 64x64x16, 256 threads, 4x4 microtile. O,Cin,P all tile-divisible.
// ---------------------------------------------------------------------------
__global__ void gemm_kernel(const float* __restrict__ W, const float* __restrict__ X,
                            float* __restrict__ Y, int Cin, int P,
                            const float* __restrict__ scale, const float* __restrict__ shift) {
    __shared__ float Ws[16][64];
    __shared__ float Xs[16][68];
    __shared__ float ssc[512], ssh[512];

    const int tid = threadIdx.x;
    const bool has_bn = (scale != nullptr);
    if (has_bn) {
        for (int c = tid; c < Cin; c += 256) { ssc[c] = scale[c]; ssh[c] = shift[c]; }
    }
    __syncthreads();

    const int o0 = blockIdx.y * 64, p0 = blockIdx.x * 64;
    const int tx = tid & 15, ty = tid >> 4;
    const int wo = tid >> 2, wk = (tid & 3) * 4;
    const int xk = tid >> 4, xp = (tid & 15) * 4;

    float acc[4][4];
    #pragma unroll
    for (int i = 0; i < 4; i++)
        #pragma unroll
        for (int j = 0; j < 4; j++) acc[i][j] = 0.f;

    const float* Wp = W + (size_t)(o0 + wo) * Cin + wk;
    const float* Xp = X + (size_t)xk * P + p0 + xp;

    for (int c0 = 0; c0 < Cin; c0 += 16) {
        float4 wv = *reinterpret_cast<const float4*>(Wp + c0);
        Ws[wk + 0][wo] = wv.x;
        Ws[wk + 1][wo] = wv.y;
        Ws[wk + 2][wo] = wv.z;
        Ws[wk + 3][wo] = wv.w;

        float4 xv = *reinterpret_cast<const float4*>(Xp + (size_t)c0 * P);
        if (has_bn) {
            float sc = ssc[c0 + xk], sh = ssh[c0 + xk];
            xv.x = fmaxf(fmaf(xv.x, sc, sh), 0.f);
            xv.y = fmaxf(fmaf(xv.y, sc, sh), 0.f);
            xv.z = fmaxf(fmaf(xv.z, sc, sh), 0.f);
            xv.w = fmaxf(fmaf(xv.w, sc, sh), 0.f);
        }
        *reinterpret_cast<float4*>(&Xs[xk][xp]) = xv;
        __syncthreads();

        #pragma unroll
        for (int kk = 0; kk < 16; kk++) {
            float4 a  = *reinterpret_cast<const float4*>(&Ws[kk][ty * 4]);
            float4 bb = *reinterpret_cast<const float4*>(&Xs[kk][tx * 4]);
            acc[0][0] += a.x * bb.x; acc[0][1] += a.x * bb.y; acc[0][2] += a.x * bb.z; acc[0][3] += a.x * bb.w;
            acc[1][0] += a.y * bb.x; acc[1][1] += a.y * bb.y; acc[1][2] += a.y * bb.z; acc[1][3] += a.y * bb.w;
            acc[2][0] += a.z * bb.x; acc[2][1] += a.z * bb.y; acc[2][2] += a.z * bb.z; acc[2][3] += a.z * bb.w;
            acc[3][0] += a.w * bb.x; acc[3][1] += a.w * bb.y; acc[3][2] += a.w * bb.z; acc[3][3] += a.w * bb.w;
        }
        __syncthreads();
    }

    #pragma unroll
    for (int i = 0; i < 4; i++) {
        float4 v = make_float4(acc[i][0], acc[i][1], acc[i][2], acc[i][3]);
        *reinterpret_cast<float4*>(&Y[(size_t)(o0 + ty * 4 + i) * P + p0 + tx * 4]) = v;
    }
}

// ---------------------------------------------------------------------------
// Per-channel sum / sumsq (double) over raw y. grid = (P/4096, C).
// ---------------------------------------------------------------------------
__global__ void stats_kernel(const float* __restrict__ Yv, double* __restrict__ sum,
                             double* __restrict__ sumsq, int P) {
    const int c = blockIdx.y;
    const float* row = Yv + (size_t)c * P;
    const int base = blockIdx.x * 4096 + threadIdx.x;
    double s = 0.0, ss = 0.0;
    #pragma unroll
    for (int u = 0; u < 16; u++) {
        int p = base + u * 256;
        if (p < P) { double v = (double)row[p]; s += v; ss += v * v; }
    }
    #pragma unroll
    for (int off = 16; off; off >>= 1) {
        s  += __shfl_down_sync(0xffffffffu, s,  off);
        ss += __shfl_down_sync(0xffffffffu, ss, off);
    }
    __shared__ double sw[8], ssw[8];
    const int lane = threadIdx.x & 31, w = threadIdx.x >> 5;
    if (lane == 0) { sw[w] = s; ssw[w] = ss; }
    __syncthreads();
    if (threadIdx.x == 0) {
        double S = 0.0, SS = 0.0;
        #pragma unroll
        for (int i = 0; i < 8; i++) { S += sw[i]; SS += ssw[i]; }
        atomicAdd(&sum[c], S);
        atomicAdd(&sumsq[c], SS);
    }
}

__global__ void finalize_kernel(const float* __restrict__ g, const float* __restrict__ bb,
                                const double* __restrict__ sum, const double* __restrict__ sumsq,
                                float* __restrict__ scale, float* __restrict__ shift,
                                int C, double invcnt) {
    int c = threadIdx.x;
    if (c >= C) return;
    double m = sum[c] * invcnt;
    double v = sumsq[c] * invcnt - m * m;
    if (v < 0.0) v = 0.0;
    float rstd = rsqrtf((float)v + 1e-5f);
    float sc = g[c] * rstd;
    scale[c] = sc;
    shift[c] = bb[c] - (float)m * sc;
}

// ---------------------------------------------------------------------------
// BN + ReLU + max over k=20; writes into concat buffer at channel offset.
// ---------------------------------------------------------------------------
__global__ void max_kernel(const float* __restrict__ Yv, const float* __restrict__ scale,
                           const float* __restrict__ shift, float* __restrict__ outp, int C) {
    const int t = blockIdx.x * 256 + threadIdx.x;
    const int c = t >> 14;            // / 16384
    const int q = t & 16383;
    const float* src = Yv + (size_t)c * P1 + (size_t)q * KNN;
    const float sc = scale[c], sh = shift[c];
    float m = 0.f;                    // relu folds: all candidates >= 0
    #pragma unroll
    for (int k = 0; k < KNN; k++) m = fmaxf(m, fmaf(src[k], sc, sh));
    outp[(size_t)c * Q + q] = m;
}

// out[b,c,n] = relu(bn(y5[c, b*N+n]))
__global__ void final_kernel(const float* __restrict__ y5, const float* __restrict__ scale,
                             const float* __restrict__ shift, float* __restrict__ out) {
    const int t = blockIdx.x * 256 + threadIdx.x;     // < 8*512*2048 = 2^23
    const int n = t & (NPTS - 1);
    const int c = (t >> 11) & 511;
    const int b = t >> 20;
    float v = y5[(size_t)c * Q + b * NPTS + n];
    out[t] = fmaxf(fmaf(v, scale[c], shift[c]), 0.f);
}

// ---------------------------------------------------------------------------
extern "C" void kernel_launch(void* const* d_in, const int* in_sizes, int n_in,
                              void* d_out, int out_size) {
    const float* x  = (const float*)d_in[0];
    const float* w1 = (const float*)d_in[1];
    const float* g1 = (const float*)d_in[2];
    const float* b1 = (const float*)d_in[3];
    const float* w2 = (const float*)d_in[4];
    const float* g2 = (const float*)d_in[5];
    const float* b2 = (const float*)d_in[6];
    const float* w3 = (const float*)d_in[7];
    const float* g3 = (const float*)d_in[8];
    const float* b3 = (const float*)d_in[9];
    const float* w4 = (const float*)d_in[10];
    const float* g4 = (const float*)d_in[11];
    const float* b4 = (const float*)d_in[12];
    const float* w5 = (const float*)d_in[13];
    const float* g5 = (const float*)d_in[14];
    const float* b5 = (const float*)d_in[15];
    float* out = (float*)d_out;

    int *idxp; float *y1, *y2, *y3, *y4, *xcat, *y5, *scal, *shif;
    double *sum, *sumsq;
    cudaGetSymbolAddress((void**)&idxp,  g_idx);
    cudaGetSymbolAddress((void**)&y1,    g_y1);
    cudaGetSymbolAddress((void**)&y2,    g_y2);
    cudaGetSymbolAddress((void**)&y3,    g_y3);
    cudaGetSymbolAddress((void**)&y4,    g_y4);
    cudaGetSymbolAddress((void**)&xcat,  g_xcat);
    cudaGetSymbolAddress((void**)&y5,    g_y5);
    cudaGetSymbolAddress((void**)&sum,   g_sum);
    cudaGetSymbolAddress((void**)&sumsq, g_sumsq);
    cudaGetSymbolAddress((void**)&scal,  g_scale);
    cudaGetSymbolAddress((void**)&shif,  g_shift);

    const double ic1 = 1.0 / (double)P1;   // BN count layers 1-4
    const double ic5 = 1.0 / (double)Q;    // BN count layer 5

    cudaMemsetAsync(sum,   0, 1024 * sizeof(double));
    cudaMemsetAsync(sumsq, 0, 1024 * sizeof(double));

    knn_kernel<<<Q / 4, 128>>>(x, idxp);
    layer1_kernel<<<P1 / 256, 256>>>(x, idxp, w1, y1);

    stats_kernel<<<dim3(80, 64), 256>>>(y1, sum + 0, sumsq + 0, P1);
    finalize_kernel<<<1, 64>>>(g1, b1, sum + 0, sumsq + 0, scal + 0, shif + 0, 64, ic1);
    max_kernel<<<64 * Q / 256, 256>>>(y1, scal + 0, shif + 0, xcat, 64);

    gemm_kernel<<<dim3(P1 / 64, 1), 256>>>(w2, y1, y2, 64, P1, scal + 0, shif + 0);
    stats_kernel<<<dim3(80, 64), 256>>>(y2, sum + 64, sumsq + 64, P1);
    finalize_kernel<<<1, 64>>>(g2, b2, sum + 64, sumsq + 64, scal + 64, shif + 64, 64, ic1);
    max_kernel<<<64 * Q / 256, 256>>>(y2, scal + 64, shif + 64, xcat + (size_t)64 * Q, 64);

    gemm_kernel<<<dim3(P1 / 64, 2), 256>>>(w3, y2, y3, 64, P1, scal + 64, shif + 64);
    stats_kernel<<<dim3(80, 128), 256>>>(y3, sum + 128, sumsq + 128, P1);
    finalize_kernel<<<1, 128>>>(g3, b3, sum + 128, sumsq + 128, scal + 128, shif + 128, 128, ic1);
    max_kernel<<<128 * Q / 256, 256>>>(y3, scal + 128, shif + 128, xcat + (size_t)128 * Q, 128);

    gemm_kernel<<<dim3(P1 / 64, 4), 256>>>(w4, y3, y4, 128, P1, scal + 128, shif + 128);
    stats_kernel<<<dim3(80, 256), 256>>>(y4, sum + 256, sumsq + 256, P1);
    finalize_kernel<<<1, 256>>>(g4, b4, sum + 256, sumsq + 256, scal + 256, shif + 256, 256, ic1);
    max_kernel<<<256 * Q / 256, 256>>>(y4, scal + 256, shif + 256, xcat + (size_t)256 * Q, 256);

    gemm_kernel<<<dim3(Q / 64, 8), 256>>>(w5, xcat, y5, 512, Q, nullptr, nullptr);
    stats_kernel<<<dim3(4, 512), 256>>>(y5, sum + 512, sumsq + 512, Q);
    finalize_kernel<<<1, 512>>>(g5, b5, sum + 512, sumsq + 512, scal + 512, shif + 512, 512, ic5);
    final_kernel<<<(BATCH * 512 * NPTS) / 256, 256>>>(y5, scal + 512, shif + 512, out);
}

// round 8
// speedup vs baseline: 1.8239x; 1.8239x over previous
#include <cuda_runtime.h>
#include <cuda_bf16.h>
#include <math_constants.h>

// ---------------------------------------------------------------------------
// DGCNN forward, B=8 C=3 N=2048 k=20, emb dims 64/64/128/256/512.
// Full fp32. kNN distance evaluation order bit-matches the reference.
// GEMM: 256x64x16 tile, 8x8 microtile, reg-staged prefetch, stats fused
// into epilogue (fp32 warp partials -> double atomics).
// ---------------------------------------------------------------------------

#define BATCH 8
#define NPTS  2048
#define KNN   20
#define Q     (BATCH * NPTS)        // 16384 (b,n) pairs
#define P1    (Q * KNN)             // 327680 (b,n,k) columns

__device__ int    g_idx[P1];
__device__ float  g_y1[(size_t)64  * P1];
__device__ float  g_y2[(size_t)64  * P1];
__device__ float  g_y3[(size_t)128 * P1];
__device__ float  g_y4[(size_t)256 * P1];
__device__ float  g_xcat[(size_t)512 * Q];
__device__ float  g_y5[(size_t)512 * Q];
__device__ double g_sum[1024];
__device__ double g_sumsq[1024];
__device__ float  g_scale[1024];
__device__ float  g_shift[1024];

// ---------------------------------------------------------------------------
// kNN: one warp per query. Distances in smem, 20 iterative argmax passes
// (tie -> lower index, matching jax.lax.top_k).
// ---------------------------------------------------------------------------
__global__ void knn_kernel(const float* __restrict__ x, int* __restrict__ idx_out) {
    __shared__ float sd[4][NPTS];
    const int warp = threadIdx.x >> 5;
    const int lane = threadIdx.x & 31;
    const int query = blockIdx.x * 4 + warp;
    const int b = query >> 11;
    const int i = query & (NPTS - 1);
    const float* xb = x + (size_t)b * 3 * NPTS;

    const float xi0 = xb[i], xi1 = xb[NPTS + i], xi2 = xb[2 * NPTS + i];
    const float xxi = __fadd_rn(__fadd_rn(__fmul_rn(xi0, xi0), __fmul_rn(xi1, xi1)),
                                __fmul_rn(xi2, xi2));

    float* d = sd[warp];
    for (int j = lane; j < NPTS; j += 32) {
        float a0 = xb[j], a1 = xb[NPTS + j], a2 = xb[2 * NPTS + j];
        float xxj = __fadd_rn(__fadd_rn(__fmul_rn(a0, a0), __fmul_rn(a1, a1)),
                              __fmul_rn(a2, a2));
        float dot = fmaf(xi2, a2, fmaf(xi1, a1, __fmul_rn(xi0, a0)));
        d[j] = __fsub_rn(__fsub_rn(2.0f * dot, xxi), xxj);
    }
    __syncwarp();

    int* out = idx_out + query * KNN;
    for (int t = 0; t < KNN; t++) {
        float best = -CUDART_INF_F;
        int bi = NPTS;
        for (int j = lane; j < NPTS; j += 32) {
            float v = d[j];
            if (v > best) { best = v; bi = j; }
        }
        #pragma unroll
        for (int off = 16; off; off >>= 1) {
            float ov = __shfl_xor_sync(0xffffffffu, best, off);
            int   oi = __shfl_xor_sync(0xffffffffu, bi, off);
            if (ov > best || (ov == best && oi < bi)) { best = ov; bi = oi; }
        }
        if (lane == 0) { out[t] = bi; d[bi] = -CUDART_INF_F; }
        __syncwarp();
    }
}

// ---------------------------------------------------------------------------
// Layer 1: gather edge feature (Cin=6) + 64x6 matvec per column, raw y out.
// ---------------------------------------------------------------------------
__global__ void layer1_kernel(const float* __restrict__ x, const int* __restrict__ idx,
                              const float* __restrict__ w1, float* __restrict__ y1) {
    __shared__ float ws[64 * 6];
    const int tid = threadIdx.x;
    for (int t = tid; t < 64 * 6; t += 256) ws[t] = w1[t];
    __syncthreads();

    const int p = blockIdx.x * 256 + tid;
    const int q = p / KNN;
    const int b = q >> 11;
    const int n = q & (NPTS - 1);
    const int j = idx[p];
    const float* xb = x + (size_t)b * 3 * NPTS;

    const float xi0 = xb[n], xi1 = xb[NPTS + n], xi2 = xb[2 * NPTS + n];
    const float f0 = xb[j] - xi0;
    const float f1 = xb[NPTS + j] - xi1;
    const float f2 = xb[2 * NPTS + j] - xi2;
    const float f3 = xi0, f4 = xi1, f5 = xi2;

    #pragma unroll 8
    for (int o = 0; o < 64; o++) {
        const float* w = ws + o * 6;
        float acc = fmaf(w[5], f5, fmaf(w[4], f4, fmaf(w[3], f3,
                    fmaf(w[2], f2, fmaf(w[1], f1, w[0] * f0)))));
        y1[(size_t)o * P1 + p] = acc;
    }
}

// ---------------------------------------------------------------------------
// SGEMM: Y[O,P] = W[O,Cin] * act(X[Cin,P]); act = relu(x*scale+shift) when
// scale != nullptr (previous layer's BN folded on load). Tile 256p x 64o x
// 16k, 256 threads, 8x8 microtile (p split as px*4 and 128+px*4 for
// conflict-free LDS.128). Per-channel sum/sumsq fused into epilogue.
// Requires P % 256 == 0, O % 64 == 0, Cin % 16 == 0.
// ---------------------------------------------------------------------------
__global__ __launch_bounds__(256, 2)
void gemm_kernel(const float* __restrict__ W, const float* __restrict__ X,
                 float* __restrict__ Y, int Cin, int P,
                 const float* __restrict__ scale, const float* __restrict__ shift,
                 double* __restrict__ sumO, double* __restrict__ sumsqO) {
    __shared__ float Xs[16][264];
    __shared__ float Ws[16][68];
    __shared__ float ssc[512], ssh[512];

    const int tid = threadIdx.x;
    const bool has_bn = (scale != nullptr);
    if (has_bn) {
        for (int c = tid; c < Cin; c += 256) { ssc[c] = scale[c]; ssh[c] = shift[c]; }
    }
    __syncthreads();

    const int p0 = blockIdx.x * 256, o0 = blockIdx.y * 64;
    const int px = tid & 31;          // p microtile: [px*4, px*4+4) and +128
    const int oy = tid >> 5;          // o microtile: [oy*8, oy*8+8)

    // global-load mapping
    const int xr = tid >> 6;          // X rows {xr, xr+4, xr+8, xr+12}
    const int xc = (tid & 63) * 4;    // X col (float4)
    const int wo = tid >> 2;          // W row (o)
    const int wc = (tid & 3) * 4;     // W col (float4)

    const float* Xg = X + (size_t)xr * P + p0 + xc;
    const float* Wg = W + (size_t)(o0 + wo) * Cin + wc;

    float acc[8][8];
    #pragma unroll
    for (int i = 0; i < 8; i++)
        #pragma unroll
        for (int j = 0; j < 8; j++) acc[i][j] = 0.f;

    float4 xf[4], wf;
    const int KT = Cin >> 4;

    // ---- load tile 0 into registers ----
    #pragma unroll
    for (int r = 0; r < 4; r++) {
        float4 v = *reinterpret_cast<const float4*>(Xg + (size_t)(r * 4) * P);
        if (has_bn) {
            float sc = ssc[xr + r * 4], sh = ssh[xr + r * 4];
            v.x = fmaxf(fmaf(v.x, sc, sh), 0.f);
            v.y = fmaxf(fmaf(v.y, sc, sh), 0.f);
            v.z = fmaxf(fmaf(v.z, sc, sh), 0.f);
            v.w = fmaxf(fmaf(v.w, sc, sh), 0.f);
        }
        xf[r] = v;
    }
    wf = *reinterpret_cast<const float4*>(Wg);

    // store tile 0
    #pragma unroll
    for (int r = 0; r < 4; r++)
        *reinterpret_cast<float4*>(&Xs[xr + r * 4][xc]) = xf[r];
    Ws[wc + 0][wo] = wf.x;
    Ws[wc + 1][wo] = wf.y;
    Ws[wc + 2][wo] = wf.z;
    Ws[wc + 3][wo] = wf.w;
    __syncthreads();

    for (int kt = 1; kt <= KT; kt++) {
        // prefetch next tile into registers (overlapped with compute)
        if (kt < KT) {
            const int c0 = kt * 16;
            #pragma unroll
            for (int r = 0; r < 4; r++) {
                float4 v = *reinterpret_cast<const float4*>(Xg + (size_t)(c0 + r * 4) * P);
                if (has_bn) {
                    float sc = ssc[c0 + xr + r * 4], sh = ssh[c0 + xr + r * 4];
                    v.x = fmaxf(fmaf(v.x, sc, sh), 0.f);
                    v.y = fmaxf(fmaf(v.y, sc, sh), 0.f);
                    v.z = fmaxf(fmaf(v.z, sc, sh), 0.f);
                    v.w = fmaxf(fmaf(v.w, sc, sh), 0.f);
                }
                xf[r] = v;
            }
            wf = *reinterpret_cast<const float4*>(Wg + c0);
        }

        // compute on current smem tile
        #pragma unroll
        for (int kk = 0; kk < 16; kk++) {
            float4 xa = *reinterpret_cast<const float4*>(&Xs[kk][px * 4]);
            float4 xb4 = *reinterpret_cast<const float4*>(&Xs[kk][128 + px * 4]);
            float4 wa = *reinterpret_cast<const float4*>(&Ws[kk][oy * 8]);
            float4 wb = *reinterpret_cast<const float4*>(&Ws[kk][oy * 8 + 4]);
            float wv[8] = {wa.x, wa.y, wa.z, wa.w, wb.x, wb.y, wb.z, wb.w};
            float xv[8] = {xa.x, xa.y, xa.z, xa.w, xb4.x, xb4.y, xb4.z, xb4.w};
            #pragma unroll
            for (int i = 0; i < 8; i++)
                #pragma unroll
                for (int j = 0; j < 8; j++)
                    acc[i][j] = fmaf(wv[i], xv[j], acc[i][j]);
        }
        __syncthreads();

        if (kt < KT) {
            #pragma unroll
            for (int r = 0; r < 4; r++)
                *reinterpret_cast<float4*>(&Xs[xr + r * 4][xc]) = xf[r];
            Ws[wc + 0][wo] = wf.x;
            Ws[wc + 1][wo] = wf.y;
            Ws[wc + 2][wo] = wf.z;
            Ws[wc + 3][wo] = wf.w;
            __syncthreads();
        }
    }

    // ---- epilogue: store Y + fused per-channel stats ----
    #pragma unroll
    for (int i = 0; i < 8; i++) {
        const size_t o = (size_t)(o0 + oy * 8 + i);
        *reinterpret_cast<float4*>(&Y[o * P + p0 + px * 4]) =
            make_float4(acc[i][0], acc[i][1], acc[i][2], acc[i][3]);
        *reinterpret_cast<float4*>(&Y[o * P + p0 + 128 + px * 4]) =
            make_float4(acc[i][4], acc[i][5], acc[i][6], acc[i][7]);
    }

    #pragma unroll
    for (int i = 0; i < 8; i++) {
        float s = 0.f, ss = 0.f;
        #pragma unroll
        for (int j = 0; j < 8; j++) {
            s += acc[i][j];
            ss = fmaf(acc[i][j], acc[i][j], ss);
        }
        #pragma unroll
        for (int off = 16; off; off >>= 1) {
            s  += __shfl_down_sync(0xffffffffu, s,  off);
            ss += __shfl_down_sync(0xffffffffu, ss, off);
        }
        if (px == 0) {
            atomicAdd(&sumO[o0 + oy * 8 + i],   (double)s);
            atomicAdd(&sumsqO[o0 + oy * 8 + i], (double)ss);
        }
    }
}

// ---------------------------------------------------------------------------
// Per-channel sum / sumsq (double) over raw y (layer 1 only).
// ---------------------------------------------------------------------------
__global__ void stats_kernel(const float* __restrict__ Yv, double* __restrict__ sum,
                             double* __restrict__ sumsq, int P) {
    const int c = blockIdx.y;
    const float* row = Yv + (size_t)c * P;
    const int base = blockIdx.x * 4096 + threadIdx.x;
    double s = 0.0, ss = 0.0;
    #pragma unroll
    for (int u = 0; u < 16; u++) {
        int p = base + u * 256;
        if (p < P) { double v = (double)row[p]; s += v; ss += v * v; }
    }
    #pragma unroll
    for (int off = 16; off; off >>= 1) {
        s  += __shfl_down_sync(0xffffffffu, s,  off);
        ss += __shfl_down_sync(0xffffffffu, ss, off);
    }
    __shared__ double sw[8], ssw[8];
    const int lane = threadIdx.x & 31, w = threadIdx.x >> 5;
    if (lane == 0) { sw[w] = s; ssw[w] = ss; }
    __syncthreads();
    if (threadIdx.x == 0) {
        double S = 0.0, SS = 0.0;
        #pragma unroll
        for (int i = 0; i < 8; i++) { S += sw[i]; SS += ssw[i]; }
        atomicAdd(&sum[c], S);
        atomicAdd(&sumsq[c], SS);
    }
}

__global__ void finalize_kernel(const float* __restrict__ g, const float* __restrict__ bb,
                                const double* __restrict__ sum, const double* __restrict__ sumsq,
                                float* __restrict__ scale, float* __restrict__ shift,
                                int C, double invcnt) {
    int c = threadIdx.x;
    if (c >= C) return;
    double m = sum[c] * invcnt;
    double v = sumsq[c] * invcnt - m * m;
    if (v < 0.0) v = 0.0;
    float rstd = rsqrtf((float)v + 1e-5f);
    float sc = g[c] * rstd;
    scale[c] = sc;
    shift[c] = bb[c] - (float)m * sc;
}

// ---------------------------------------------------------------------------
// BN + ReLU + max over k=20; writes into concat buffer at channel offset.
// ---------------------------------------------------------------------------
__global__ void max_kernel(const float* __restrict__ Yv, const float* __restrict__ scale,
                           const float* __restrict__ shift, float* __restrict__ outp, int C) {
    const int t = blockIdx.x * 256 + threadIdx.x;
    const int c = t >> 14;            // / 16384
    const int q = t & 16383;
    const float* src = Yv + (size_t)c * P1 + (size_t)q * KNN;
    const float sc = scale[c], sh = shift[c];
    float m = 0.f;                    // relu folds: all candidates >= 0
    #pragma unroll
    for (int k = 0; k < KNN; k++) m = fmaxf(m, fmaf(src[k], sc, sh));
    outp[(size_t)c * Q + q] = m;
}

// out[b,c,n] = relu(bn(y5[c, b*N+n]))
__global__ void final_kernel(const float* __restrict__ y5, const float* __restrict__ scale,
                             const float* __restrict__ shift, float* __restrict__ out) {
    const int t = blockIdx.x * 256 + threadIdx.x;     // < 8*512*2048 = 2^23
    const int n = t & (NPTS - 1);
    const int c = (t >> 11) & 511;
    const int b = t >> 20;
    float v = y5[(size_t)c * Q + b * NPTS + n];
    out[t] = fmaxf(fmaf(v, scale[c], shift[c]), 0.f);
}

// ---------------------------------------------------------------------------
extern "C" void kernel_launch(void* const* d_in, const int* in_sizes, int n_in,
                              void* d_out, int out_size) {
    const float* x  = (const float*)d_in[0];
    const float* w1 = (const float*)d_in[1];
    const float* g1 = (const float*)d_in[2];
    const float* b1 = (const float*)d_in[3];
    const float* w2 = (const float*)d_in[4];
    const float* g2 = (const float*)d_in[5];
    const float* b2 = (const float*)d_in[6];
    const float* w3 = (const float*)d_in[7];
    const float* g3 = (const float*)d_in[8];
    const float* b3 = (const float*)d_in[9];
    const float* w4 = (const float*)d_in[10];
    const float* g4 = (const float*)d_in[11];
    const float* b4 = (const float*)d_in[12];
    const float* w5 = (const float*)d_in[13];
    const float* g5 = (const float*)d_in[14];
    const float* b5 = (const float*)d_in[15];
    float* out = (float*)d_out;

    int *idxp; float *y1, *y2, *y3, *y4, *xcat, *y5, *scal, *shif;
    double *sum, *sumsq;
    cudaGetSymbolAddress((void**)&idxp,  g_idx);
    cudaGetSymbolAddress((void**)&y1,    g_y1);
    cudaGetSymbolAddress((void**)&y2,    g_y2);
    cudaGetSymbolAddress((void**)&y3,    g_y3);
    cudaGetSymbolAddress((void**)&y4,    g_y4);
    cudaGetSymbolAddress((void**)&xcat,  g_xcat);
    cudaGetSymbolAddress((void**)&y5,    g_y5);
    cudaGetSymbolAddress((void**)&sum,   g_sum);
    cudaGetSymbolAddress((void**)&sumsq, g_sumsq);
    cudaGetSymbolAddress((void**)&scal,  g_scale);
    cudaGetSymbolAddress((void**)&shif,  g_shift);

    const double ic1 = 1.0 / (double)P1;   // BN count layers 1-4
    const double ic5 = 1.0 / (double)Q;    // BN count layer 5

    cudaMemsetAsync(sum,   0, 1024 * sizeof(double));
    cudaMemsetAsync(sumsq, 0, 1024 * sizeof(double));

    knn_kernel<<<Q / 4, 128>>>(x, idxp);
    layer1_kernel<<<P1 / 256, 256>>>(x, idxp, w1, y1);

    stats_kernel<<<dim3(80, 64), 256>>>(y1, sum + 0, sumsq + 0, P1);
    finalize_kernel<<<1, 64>>>(g1, b1, sum + 0, sumsq + 0, scal + 0, shif + 0, 64, ic1);
    max_kernel<<<64 * Q / 256, 256>>>(y1, scal + 0, shif + 0, xcat, 64);

    gemm_kernel<<<dim3(P1 / 256, 1), 256>>>(w2, y1, y2, 64, P1, scal + 0, shif + 0,
                                            sum + 64, sumsq + 64);
    finalize_kernel<<<1, 64>>>(g2, b2, sum + 64, sumsq + 64, scal + 64, shif + 64, 64, ic1);
    max_kernel<<<64 * Q / 256, 256>>>(y2, scal + 64, shif + 64, xcat + (size_t)64 * Q, 64);

    gemm_kernel<<<dim3(P1 / 256, 2), 256>>>(w3, y2, y3, 64, P1, scal + 64, shif + 64,
                                            sum + 128, sumsq + 128);
    finalize_kernel<<<1, 128>>>(g3, b3, sum + 128, sumsq + 128, scal + 128, shif + 128, 128, ic1);
    max_kernel<<<128 * Q / 256, 256>>>(y3, scal + 128, shif + 128, xcat + (size_t)128 * Q, 128);

    gemm_kernel<<<dim3(P1 / 256, 4), 256>>>(w4, y3, y4, 128, P1, scal + 128, shif + 128,
                                            sum + 256, sumsq + 256);
    finalize_kernel<<<1, 256>>>(g4, b4, sum + 256, sumsq + 256, scal + 256, shif + 256, 256, ic1);
    max_kernel<<<256 * Q / 256, 256>>>(y4, scal + 256, shif + 256, xcat + (size_t)256 * Q, 256);

    gemm_kernel<<<dim3(Q / 256, 8), 256>>>(w5, xcat, y5, 512, Q, nullptr, nullptr,
                                           sum + 512, sumsq + 512);
    finalize_kernel<<<1, 512>>>(g5, b5, sum + 512, sumsq + 512, scal + 512, shif + 512, 512, ic5);
    final_kernel<<<(BATCH * 512 * NPTS) / 256, 256>>>(y5, scal + 512, shif + 512, out);
}